// round 5
// baseline (speedup 1.0000x reference)
#include <cuda_runtime.h>
#include <cuda_fp16.h>
#include <cstdint>
#include <cstring>

// Problem constants (fixed shapes)
#define BATCH   2
#define NLIGHT  8
#define HDIM    128
#define D0      128
#define D1      128
#define D2      128
#define NCAM    3
#define NNZ     2097152              // 2^21
#define XYZ     (D0*D1*D2)           // 2^21
#define ROWS_T  (D0*D1)              // 16384
#define BN      (BATCH*NLIGHT)       // 16
#define OUTSZ   (BATCH*NLIGHT*NCAM*D0*D1)  // 786432

// exponnorm params
#define P_K     1.790987517302874f
#define P_LOC   -0.08208043639065216f
#define P_SCALE 0.05720079131427573f

// ---------------- bit-cast helpers (no such intrinsics in this toolkit) ----
__device__ __forceinline__ unsigned h2_to_u(half2 h) {
    __half2_raw r = *reinterpret_cast<__half2_raw*>(&h);
    return (unsigned)r.x | ((unsigned)r.y << 16);
}
__device__ __forceinline__ half2 u_to_h2(unsigned u) {
    __half2_raw r;
    r.x = (unsigned short)(u & 0xFFFFu);
    r.y = (unsigned short)(u >> 16);
    return *reinterpret_cast<half2*>(&r);
}

// ---------------- device scratch (static, no allocations) ----------------
__device__ float g_light8[ROWS_T*NLIGHT];   // light[xz][n] fp32, 512KB
// Per-col record, 32B: {d0.f32, d1.f32, l01.h2, l23.h2, l45.h2, l67.h2, pad8}
__device__ uint4 g_rec[XYZ*2];              // 64MB
__device__ float g_acc[NCAM*ROWS_T*BN];     // accumulator [c][row][bn], 3MB

// ---------------- threefry2x32 ----------------
__host__ __device__ __forceinline__ unsigned rotl32(unsigned x, int r) {
    return (x << r) | (x >> (32 - r));
}

__host__ __device__ __forceinline__ void threefry2x32(
    unsigned k0, unsigned k1, unsigned x0, unsigned x1,
    unsigned* o0, unsigned* o1)
{
    unsigned ks0 = k0, ks1 = k1, ks2 = k0 ^ k1 ^ 0x1BD11BDAu;
    x0 += ks0; x1 += ks1;
#define TF_R4(a,b,c,d) \
    x0 += x1; x1 = rotl32(x1,a); x1 ^= x0; \
    x0 += x1; x1 = rotl32(x1,b); x1 ^= x0; \
    x0 += x1; x1 = rotl32(x1,c); x1 ^= x0; \
    x0 += x1; x1 = rotl32(x1,d); x1 ^= x0;
    TF_R4(13,15,26,6);  x0 += ks1; x1 += ks2 + 1u;
    TF_R4(17,29,16,24); x0 += ks2; x1 += ks0 + 2u;
    TF_R4(13,15,26,6);  x0 += ks0; x1 += ks1 + 3u;
    TF_R4(17,29,16,24); x0 += ks1; x1 += ks2 + 4u;
    TF_R4(13,15,26,6);  x0 += ks2; x1 += ks0 + 5u;
#undef TF_R4
    *o0 = x0; *o1 = x1;
}

// Partitionable threefry random_bits: element i -> counter (0, i), out0 ^ out1.
__device__ __forceinline__ unsigned tf_bits_part(unsigned k0, unsigned k1, unsigned i) {
    unsigned o0, o1;
    threefry2x32(k0, k1, 0u, i, &o0, &o1);
    return o0 ^ o1;
}

// ---------------- kernels ----------------

// Fused: each block redundantly computes w = sigmoid(lp)/||sigmoid(lp)||,
// then light8[xz][n] = sum_h light_info[h][xz] * w[n][h] for its 256 xz.
__global__ void __launch_bounds__(256) k_light(
    const float* __restrict__ lp, const float* __restrict__ li)
{
    __shared__ float w[NLIGHT*HDIM];
    __shared__ float red[8];
    int t = threadIdx.x;

    float sumsq = 0.0f;
    #pragma unroll
    for (int j = 0; j < 4; j++) {
        int i = t + j * 256;
        float s = 1.0f / (1.0f + expf(-lp[i]));
        w[i] = s;
        sumsq += s * s;
    }
    #pragma unroll
    for (int off = 16; off > 0; off >>= 1)
        sumsq += __shfl_xor_sync(0xFFFFFFFFu, sumsq, off);
    if ((t & 31) == 0) red[t >> 5] = sumsq;
    __syncthreads();
    float inv;
    {
        float tot = red[0];
        #pragma unroll
        for (int k = 1; k < 8; k++) tot += red[k];
        inv = rsqrtf(tot);
    }
    __syncthreads();
    #pragma unroll
    for (int j = 0; j < 4; j++) w[t + j * 256] *= inv;
    __syncthreads();

    int xz = blockIdx.x * 256 + t;
    float acc[NLIGHT];
    #pragma unroll
    for (int n = 0; n < NLIGHT; n++) acc[n] = 0.0f;
    #pragma unroll 4
    for (int h = 0; h < HDIM; h++) {
        float v = li[h * ROWS_T + xz];
        #pragma unroll
        for (int n = 0; n < NLIGHT; n++)
            acc[n] = fmaf(v, w[n * HDIM + h], acc[n]);
    }
    #pragma unroll
    for (int n = 0; n < NLIGHT; n++)
        g_light8[xz * NLIGHT + n] = acc[n];
}

// Build per-col records (blocks 0..127, one x-slab each) and zero the
// accumulator (blocks 128..319).
__global__ void __launch_bounds__(256) k_build(const float* __restrict__ dv) {
    int bid = blockIdx.x;
    int t = threadIdx.x;

    if (bid >= 128) {
        // zero acc: 3MB = 196608 float4; 192 blocks * 256 threads * 4
        float4* av = reinterpret_cast<float4*>(g_acc);
        int base = (bid - 128) * 1024;
        #pragma unroll
        for (int j = 0; j < 4; j++)
            av[base + j * 256 + t] = make_float4(0.f, 0.f, 0.f, 0.f);
        return;
    }

    int x = bid;
    // load light8 row-block for this x: 128 z * 8 n floats -> 512 packed half2
    __shared__ unsigned sl[512];   // sl[z*4 + p] = pack(l(2p), l(2p+1))
    {
        const float2* src = reinterpret_cast<const float2*>(g_light8 + (x << 10));
        for (int i = t; i < 512; i += 256) {
            float2 f = src[i];
            sl[i] = h2_to_u(__floats2half2_rn(f.x, f.y));
        }
    }
    __syncthreads();

    int base = x << 14;     // first col of this x-slab
    #pragma unroll 4
    for (int it = 0; it < 64; it++) {
        int yz = it * 256 + t;
        int z = yz & 127;
        int col = base + yz;
        float a = dv[col];
        float b = dv[XYZ + col];
        const unsigned* lz = &sl[z << 2];
        uint4 r0, r1;
        r0.x = __float_as_uint(a);
        r0.y = __float_as_uint(b);
        r0.z = lz[0];
        r0.w = lz[1];
        r1.x = lz[2];
        r1.y = lz[3];
        r1.z = 0u; r1.w = 0u;
        g_rec[col * 2 + 0] = r0;
        g_rec[col * 2 + 1] = r1;
    }
}

__device__ __forceinline__ void red_v4(float* p, float a, float b, float c, float d) {
    unsigned long long gp = __cvta_generic_to_global((void*)p);
    asm volatile("red.global.add.v4.f32 [%0], {%1,%2,%3,%4};"
                 :: "l"(gp), "f"(a), "f"(b), "f"(c), "f"(d) : "memory");
}

// scatter: one thread per 4 consecutive nnz (same camera; NNZ % 4 == 0)
__global__ void __launch_bounds__(256) k_scatter(
    const int* __restrict__ rows, const int* __restrict__ cols,
    const float* __restrict__ vals)
{
    int t = blockIdx.x * 256 + threadIdx.x;     // 0 .. 3*NNZ/4-1
    int cam = t >> 19;                           // NNZ/4 = 2^19 per camera

    int4   r4 = reinterpret_cast<const int4*>(rows)[t];
    int4   c4 = reinterpret_cast<const int4*>(cols)[t];
    float4 v4 = reinterpret_cast<const float4*>(vals)[t];

    int rr[4] = {r4.x, r4.y, r4.z, r4.w};
    int cc[4] = {c4.x, c4.y, c4.z, c4.w};
    float vv[4] = {v4.x, v4.y, v4.z, v4.w};

    // batched record gathers (one 32B sector each)
    uint4 p[4];
    uint2 q[4];
    #pragma unroll
    for (int j = 0; j < 4; j++)
        p[j] = __ldg(&g_rec[cc[j] * 2]);
    #pragma unroll
    for (int j = 0; j < 4; j++)
        q[j] = __ldg(reinterpret_cast<const uint2*>(&g_rec[cc[j] * 2 + 1]));

    float* cbase = g_acc + ((unsigned)cam << 18);   // cam * 16384 * 16
    #pragma unroll
    for (int j = 0; j < 4; j++) {
        float a = vv[j] * __uint_as_float(p[j].x);
        float b = vv[j] * __uint_as_float(p[j].y);
        float2 l01 = __half22float2(u_to_h2(p[j].z));
        float2 l23 = __half22float2(u_to_h2(p[j].w));
        float2 l45 = __half22float2(u_to_h2(q[j].x));
        float2 l67 = __half22float2(u_to_h2(q[j].y));
        float* base = cbase + ((unsigned)rr[j] << 4);
        red_v4(base + 0,  a*l01.x, a*l01.y, a*l23.x, a*l23.y);
        red_v4(base + 4,  a*l45.x, a*l45.y, a*l67.x, a*l67.y);
        red_v4(base + 8,  b*l01.x, b*l01.y, b*l23.x, b*l23.y);
        red_v4(base + 12, b*l45.x, b*l45.y, b*l67.x, b*l67.y);
    }
}

// finalize: out[b,n,c,X,Y] = acc[c][X*128+Y][b*8+n] * (1 + noise[i])
__global__ void __launch_bounds__(256) k_final(
    float* __restrict__ out,
    unsigned kn0, unsigned kn1, unsigned ke0, unsigned ke1)
{
    int i = blockIdx.x * 256 + threadIdx.x;   // 0 .. OUTSZ-1
    int r  = i & (ROWS_T - 1);
    int t  = i >> 14;          // bn*3 + c
    int bn = t / NCAM;
    int c  = t - bn * NCAM;

    float x = g_acc[((((unsigned)c << 14) + (unsigned)r) << 4) + (unsigned)bn];

    // normal(kn): uniform in [nextafter(-1,0), 1), z = sqrt(2)*erfinv(u)
    unsigned nb = tf_bits_part(kn0, kn1, (unsigned)i);
    float fn = __uint_as_float((nb >> 9) | 0x3f800000u) - 1.0f;
    const float lo = -0.99999994f;                 // nextafterf(-1,0)
    float u = fmaxf(lo, fn * (1.0f - lo) + lo);
    float nrm = 1.41421356237309515f * erfinvf(u);

    // exponential(ke): u in [0,1), e = -log1p(-u)
    unsigned eb = tf_bits_part(ke0, ke1, (unsigned)i);
    float fe = __uint_as_float((eb >> 9) | 0x3f800000u) - 1.0f;
    float ex = -log1pf(-fe);

    float noise = (P_LOC + P_SCALE * nrm) + (P_K * P_SCALE) * ex;
    out[i] = x + x * noise;
}

// ---------------- launch ----------------
extern "C" void kernel_launch(void* const* d_in, const int* in_sizes, int n_in,
                              void* d_out, int out_size)
{
    const float* density    = (const float*)d_in[0];  // (2,128,128,128)
    const float* light_pat  = (const float*)d_in[1];  // (8,128)
    const float* light_info = (const float*)d_in[2];  // (128,128,128)
    const int*   ray_rows   = (const int*)d_in[3];    // (3, NNZ)
    const int*   ray_cols   = (const int*)d_in[4];    // (3, NNZ)
    const float* ray_vals   = (const float*)d_in[5];  // (3, NNZ)
    float* out = (float*)d_out;

    // jax.random.key(42); partitionable split(key,2): subkey_i = threefry(k,(0,i))
    unsigned kn0, kn1, ke0, ke1;
    threefry2x32(0u, 42u, 0u, 0u, &kn0, &kn1);   // subkey 0 -> normal
    threefry2x32(0u, 42u, 0u, 1u, &ke0, &ke1);   // subkey 1 -> exponential

    k_light<<<ROWS_T/256, 256>>>(light_pat, light_info);
    k_build<<<320, 256>>>(density);
    k_scatter<<<(NCAM*NNZ/4)/256, 256>>>(ray_rows, ray_cols, ray_vals);
    k_final<<<OUTSZ/256, 256>>>(out, kn0, kn1, ke0, ke1);
}

// round 6
// speedup vs baseline: 1.2088x; 1.2088x over previous
#include <cuda_runtime.h>
#include <cuda_fp16.h>
#include <cstdint>

// Problem constants (fixed shapes)
#define BATCH   2
#define NLIGHT  8
#define HDIM    128
#define D0      128
#define D1      128
#define D2      128
#define NCAM    3
#define NNZ     2097152              // 2^21
#define XYZ     (D0*D1*D2)           // 2^21
#define ROWS_T  (D0*D1)              // 16384
#define BN      (BATCH*NLIGHT)       // 16
#define OUTSZ   (BATCH*NLIGHT*NCAM*D0*D1)  // 786432

// exponnorm params
#define P_K     1.790987517302874f
#define P_LOC   -0.08208043639065216f
#define P_SCALE 0.05720079131427573f

// ---------------- bit-cast helpers ----------------
__device__ __forceinline__ unsigned h2_to_u(half2 h) {
    __half2_raw r = *reinterpret_cast<__half2_raw*>(&h);
    return (unsigned)r.x | ((unsigned)r.y << 16);
}
__device__ __forceinline__ half2 u_to_h2(unsigned u) {
    __half2_raw r;
    r.x = (unsigned short)(u & 0xFFFFu);
    r.y = (unsigned short)(u >> 16);
    return *reinterpret_cast<half2*>(&r);
}

// ---------------- device scratch (static, no allocations) ----------------
__device__ uint4  g_lh[ROWS_T];             // light[xz] as 8 x fp16, 16B each, 256KB
__device__ float2 g_d2[XYZ];                // density transposed [col](b0,b1), 16MB
__device__ float  g_acc[NCAM*ROWS_T*BN];    // accumulator [c][row][bn], 3MB

// ---------------- threefry2x32 ----------------
__host__ __device__ __forceinline__ unsigned rotl32(unsigned x, int r) {
    return (x << r) | (x >> (32 - r));
}

__host__ __device__ __forceinline__ void threefry2x32(
    unsigned k0, unsigned k1, unsigned x0, unsigned x1,
    unsigned* o0, unsigned* o1)
{
    unsigned ks0 = k0, ks1 = k1, ks2 = k0 ^ k1 ^ 0x1BD11BDAu;
    x0 += ks0; x1 += ks1;
#define TF_R4(a,b,c,d) \
    x0 += x1; x1 = rotl32(x1,a); x1 ^= x0; \
    x0 += x1; x1 = rotl32(x1,b); x1 ^= x0; \
    x0 += x1; x1 = rotl32(x1,c); x1 ^= x0; \
    x0 += x1; x1 = rotl32(x1,d); x1 ^= x0;
    TF_R4(13,15,26,6);  x0 += ks1; x1 += ks2 + 1u;
    TF_R4(17,29,16,24); x0 += ks2; x1 += ks0 + 2u;
    TF_R4(13,15,26,6);  x0 += ks0; x1 += ks1 + 3u;
    TF_R4(17,29,16,24); x0 += ks1; x1 += ks2 + 4u;
    TF_R4(13,15,26,6);  x0 += ks2; x1 += ks0 + 5u;
#undef TF_R4
    *o0 = x0; *o1 = x1;
}

// Partitionable threefry random_bits: element i -> counter (0, i), out0 ^ out1.
__device__ __forceinline__ unsigned tf_bits_part(unsigned k0, unsigned k1, unsigned i) {
    unsigned o0, o1;
    threefry2x32(k0, k1, 0u, i, &o0, &o1);
    return o0 ^ o1;
}

// ---------------- kernels ----------------

// Fused: each block redundantly computes w = sigmoid(lp)/||sigmoid(lp)||,
// then light[xz][n] = sum_h light_info[h][xz] * w[n][h], stored as 8 x fp16.
__global__ void __launch_bounds__(256) k_light(
    const float* __restrict__ lp, const float* __restrict__ li)
{
    __shared__ float w[NLIGHT*HDIM];
    __shared__ float red[8];
    int t = threadIdx.x;

    float sumsq = 0.0f;
    #pragma unroll
    for (int j = 0; j < 4; j++) {
        int i = t + j * 256;
        float s = 1.0f / (1.0f + expf(-lp[i]));
        w[i] = s;
        sumsq += s * s;
    }
    #pragma unroll
    for (int off = 16; off > 0; off >>= 1)
        sumsq += __shfl_xor_sync(0xFFFFFFFFu, sumsq, off);
    if ((t & 31) == 0) red[t >> 5] = sumsq;
    __syncthreads();
    float inv;
    {
        float tot = red[0];
        #pragma unroll
        for (int k = 1; k < 8; k++) tot += red[k];
        inv = rsqrtf(tot);
    }
    __syncthreads();
    #pragma unroll
    for (int j = 0; j < 4; j++) w[t + j * 256] *= inv;
    __syncthreads();

    int xz = blockIdx.x * 256 + t;
    float acc[NLIGHT];
    #pragma unroll
    for (int n = 0; n < NLIGHT; n++) acc[n] = 0.0f;
    #pragma unroll 4
    for (int h = 0; h < HDIM; h++) {
        float v = li[h * ROWS_T + xz];
        #pragma unroll
        for (int n = 0; n < NLIGHT; n++)
            acc[n] = fmaf(v, w[n * HDIM + h], acc[n]);
    }
    uint4 packed;
    packed.x = h2_to_u(__floats2half2_rn(acc[0], acc[1]));
    packed.y = h2_to_u(__floats2half2_rn(acc[2], acc[3]));
    packed.z = h2_to_u(__floats2half2_rn(acc[4], acc[5]));
    packed.w = h2_to_u(__floats2half2_rn(acc[6], acc[7]));
    g_lh[xz] = packed;
}

// density transpose, float4-vectorized: d2[col] = (dv[0][col], dv[1][col])
__global__ void __launch_bounds__(256) k_d2(const float* __restrict__ dv) {
    int i = (blockIdx.x * 256 + threadIdx.x) * 4;
    float4 a = *reinterpret_cast<const float4*>(dv + i);
    float4 b = *reinterpret_cast<const float4*>(dv + XYZ + i);
    float4* o = reinterpret_cast<float4*>(g_d2 + i);
    o[0] = make_float4(a.x, b.x, a.y, b.y);
    o[1] = make_float4(a.z, b.z, a.w, b.w);
}

// zero accumulator (float4)
__global__ void __launch_bounds__(256) k_zero() {
    int i = blockIdx.x * 256 + threadIdx.x;
    reinterpret_cast<float4*>(g_acc)[i] = make_float4(0.f, 0.f, 0.f, 0.f);
}

__device__ __forceinline__ void red_v4(float* p, float a, float b, float c, float d) {
    unsigned long long gp = __cvta_generic_to_global((void*)p);
    asm volatile("red.global.add.v4.f32 [%0], {%1,%2,%3,%4};"
                 :: "l"(gp), "f"(a), "f"(b), "f"(c), "f"(d) : "memory");
}

// scatter: one thread per 4 consecutive nnz (same camera; NNZ % 4 == 0)
__global__ void __launch_bounds__(256) k_scatter(
    const int* __restrict__ rows, const int* __restrict__ cols,
    const float* __restrict__ vals)
{
    int t = blockIdx.x * 256 + threadIdx.x;     // 0 .. 3*NNZ/4-1
    int cam = t >> 19;                           // NNZ/4 = 2^19 per camera

    // read-once streams: evict-first so they don't displace the gather tables
    int4   r4 = __ldcs(reinterpret_cast<const int4*>(rows) + t);
    int4   c4 = __ldcs(reinterpret_cast<const int4*>(cols) + t);
    float4 v4 = __ldcs(reinterpret_cast<const float4*>(vals) + t);

    int rr[4] = {r4.x, r4.y, r4.z, r4.w};
    int cc[4] = {c4.x, c4.y, c4.z, c4.w};
    float vv[4] = {v4.x, v4.y, v4.z, v4.w};

    // d2 gather: L2-only (.cg) — random over 16MB, keep it out of L1
    float2 d[4];
    #pragma unroll
    for (int j = 0; j < 4; j++) d[j] = __ldcg(&g_d2[cc[j]]);

    // light gather: L1-cached (.ca) — 256KB table, mostly L1-resident
    uint4 l[4];
    #pragma unroll
    for (int j = 0; j < 4; j++) {
        int xz = ((cc[j] >> 14) << 7) | (cc[j] & 127);
        l[j] = __ldg(&g_lh[xz]);
    }

    float* cbase = g_acc + ((unsigned)cam << 18);   // cam * 16384 * 16
    #pragma unroll
    for (int j = 0; j < 4; j++) {
        float a = vv[j] * d[j].x;
        float b = vv[j] * d[j].y;
        float2 l01 = __half22float2(u_to_h2(l[j].x));
        float2 l23 = __half22float2(u_to_h2(l[j].y));
        float2 l45 = __half22float2(u_to_h2(l[j].z));
        float2 l67 = __half22float2(u_to_h2(l[j].w));
        float* base = cbase + ((unsigned)rr[j] << 4);
        red_v4(base + 0,  a*l01.x, a*l01.y, a*l23.x, a*l23.y);
        red_v4(base + 4,  a*l45.x, a*l45.y, a*l67.x, a*l67.y);
        red_v4(base + 8,  b*l01.x, b*l01.y, b*l23.x, b*l23.y);
        red_v4(base + 12, b*l45.x, b*l45.y, b*l67.x, b*l67.y);
    }
}

// finalize: out[b,n,c,X,Y] = acc[c][X*128+Y][b*8+n] * (1 + noise[i])
__global__ void __launch_bounds__(256) k_final(
    float* __restrict__ out,
    unsigned kn0, unsigned kn1, unsigned ke0, unsigned ke1)
{
    int i = blockIdx.x * 256 + threadIdx.x;   // 0 .. OUTSZ-1
    int r  = i & (ROWS_T - 1);
    int t  = i >> 14;          // bn*3 + c
    int bn = t / NCAM;
    int c  = t - bn * NCAM;

    float x = g_acc[((((unsigned)c << 14) + (unsigned)r) << 4) + (unsigned)bn];

    // normal(kn): uniform in [nextafter(-1,0), 1), z = sqrt(2)*erfinv(u)
    unsigned nb = tf_bits_part(kn0, kn1, (unsigned)i);
    float fn = __uint_as_float((nb >> 9) | 0x3f800000u) - 1.0f;
    const float lo = -0.99999994f;                 // nextafterf(-1,0)
    float u = fmaxf(lo, fn * (1.0f - lo) + lo);
    float nrm = 1.41421356237309515f * erfinvf(u);

    // exponential(ke): u in [0,1), e = -log1p(-u)
    unsigned eb = tf_bits_part(ke0, ke1, (unsigned)i);
    float fe = __uint_as_float((eb >> 9) | 0x3f800000u) - 1.0f;
    float ex = -log1pf(-fe);

    float noise = (P_LOC + P_SCALE * nrm) + (P_K * P_SCALE) * ex;
    out[i] = x + x * noise;
}

// ---------------- launch ----------------
extern "C" void kernel_launch(void* const* d_in, const int* in_sizes, int n_in,
                              void* d_out, int out_size)
{
    const float* density    = (const float*)d_in[0];  // (2,128,128,128)
    const float* light_pat  = (const float*)d_in[1];  // (8,128)
    const float* light_info = (const float*)d_in[2];  // (128,128,128)
    const int*   ray_rows   = (const int*)d_in[3];    // (3, NNZ)
    const int*   ray_cols   = (const int*)d_in[4];    // (3, NNZ)
    const float* ray_vals   = (const float*)d_in[5];  // (3, NNZ)
    float* out = (float*)d_out;

    // jax.random.key(42); partitionable split(key,2): subkey_i = threefry(k,(0,i))
    unsigned kn0, kn1, ke0, ke1;
    threefry2x32(0u, 42u, 0u, 0u, &kn0, &kn1);   // subkey 0 -> normal
    threefry2x32(0u, 42u, 0u, 1u, &ke0, &ke1);   // subkey 1 -> exponential

    k_light<<<ROWS_T/256, 256>>>(light_pat, light_info);
    k_d2<<<XYZ/(256*4), 256>>>(density);
    k_zero<<<(NCAM*ROWS_T*BN/4)/256, 256>>>();
    k_scatter<<<(NCAM*NNZ/4)/256, 256>>>(ray_rows, ray_cols, ray_vals);
    k_final<<<OUTSZ/256, 256>>>(out, kn0, kn1, ke0, ke1);
}